// round 11
// baseline (speedup 1.0000x reference)
#include <cuda_runtime.h>
#include <cuda_bf16.h>
#include <math.h>
#include <cstdint>

#define BATCH 2
#define SEQ 2048
#define DMODEL 2048
#define NH 16
#define NKV 4
#define HD 128
#define NREP 4
#define QKV_OUT 3072   // (16 + 2*4) * 128
#define BSTOT (BATCH*SEQ)

// ---------------- scratch (device globals; no allocation allowed) ----------
__device__ float g_qkv [BSTOT * QKV_OUT];        // 48 MB
__device__ float g_q   [BATCH * NH  * SEQ * HD]; // 32 MB  (tf32-rounded)
__device__ float g_k   [BATCH * NKV * SEQ * HD]; //  8 MB  (tf32-rounded)
__device__ float g_v   [BATCH * NKV * SEQ * HD]; //  8 MB  (tf32-rounded)
__device__ float g_gate[BSTOT * NH];             // 0.5 MB
__device__ float g_attn[BSTOT * (NH*HD)];        // 32 MB

// ========================== helpers ========================================
__device__ __forceinline__ float tf32r_(float x) {
    uint32_t r;
    asm("cvt.rna.tf32.f32 %0, %1;" : "=r"(r) : "f"(x));
    return __uint_as_float(r);
}
__device__ __forceinline__ uint32_t tf32u_(float x) {
    uint32_t r;
    asm("cvt.rna.tf32.f32 %0, %1;" : "=r"(r) : "f"(x));
    return r;
}
__device__ __forceinline__ float4 tf32r4_(float4 v) {
    v.x = tf32r_(v.x); v.y = tf32r_(v.y);
    v.z = tf32r_(v.z); v.w = tf32r_(v.w);
    return v;
}
__device__ __forceinline__ uint32_t smem_u32_(const void* p) {
    uint32_t a;
    asm("{ .reg .u64 t; cvta.to.shared.u64 t, %1; cvt.u32.u64 %0, t; }"
        : "=r"(a) : "l"(p));
    return a;
}
__device__ __forceinline__ void cpa16_(uint32_t dst, const void* src) {
    asm volatile("cp.async.cg.shared.global [%0], [%1], 16;"
                 :: "r"(dst), "l"(src));
}
#define CP_COMMIT() asm volatile("cp.async.commit_group;" ::: "memory")
#define CP_WAIT0()  asm volatile("cp.async.wait_group 0;" ::: "memory")
#define CP_WAIT1()  asm volatile("cp.async.wait_group 1;" ::: "memory")
#define CP_WAIT2()  asm volatile("cp.async.wait_group 2;" ::: "memory")

// D += A(16x8,row) * B(8x8,col)  tf32 inputs, f32 accum
__device__ __forceinline__ void mma_tf32_(float* d, const uint32_t* a,
                                          const uint32_t* b) {
    asm volatile(
        "mma.sync.aligned.m16n8k8.row.col.f32.tf32.tf32.f32 "
        "{%0,%1,%2,%3}, {%4,%5,%6,%7}, {%8,%9}, {%0,%1,%2,%3};\n"
        : "+f"(d[0]), "+f"(d[1]), "+f"(d[2]), "+f"(d[3])
        : "r"(a[0]), "r"(a[1]), "r"(a[2]), "r"(a[3]),
          "r"(b[0]), "r"(b[1]));
}

// ===== tf32 mma.sync NT GEMM, cp.async 3-stage: C[M,N] = A * B^T ===========
// 128x128 CTA tile, BK=16, 8 warps (warp tile 32x64), pitch-20 smem.
#define GP 20
#define GSTW (128 * GP)          // words per operand per stage
#define GSTAGE (2 * GSTW)        // A+B per stage
#define GEMM_SMEM (3 * GSTAGE * 4)  // 61440 bytes

__global__ __launch_bounds__(256, 2)
void gemm_tf32mma(const float* __restrict__ A, const float* __restrict__ Bm,
                  float* __restrict__ C, int M, int N, int K) {
    extern __shared__ float smg[];
    const uint32_t sb = smem_u32_(smg);

    const int tid  = threadIdx.x;
    const int lane = tid & 31;
    const int wid  = tid >> 5;
    const int wm   = wid & 3;
    const int wn   = wid >> 2;
    const int m0   = blockIdx.y * 128;
    const int n0   = blockIdx.x * 128;
    const int lg   = lane >> 2;
    const int lq   = lane & 3;

    float acc[2][8][4];
#pragma unroll
    for (int mt = 0; mt < 2; ++mt)
#pragma unroll
        for (int nt = 0; nt < 8; ++nt)
#pragma unroll
            for (int j = 0; j < 4; ++j) acc[mt][nt][j] = 0.f;

    const int row_ld = tid >> 2;         // 0..63 (handles 2 rows via +64)
    const int c4_ld  = tid & 3;

    auto ISSUE = [&](int t) {
        const int st = (t % 3);
        const int k0 = t << 4;
        const uint32_t base = sb + (uint32_t)(st * GSTAGE) * 4;
#pragma unroll
        for (int i = 0; i < 2; ++i) {
            int row = row_ld + 64 * i;
            uint32_t off = (uint32_t)(row * GP + 4 * c4_ld) * 4;
            cpa16_(base + off,
                   A + (size_t)(m0 + row) * K + k0 + 4 * c4_ld);
            cpa16_(base + (uint32_t)GSTW * 4 + off,
                   Bm + (size_t)(n0 + row) * K + k0 + 4 * c4_ld);
        }
        CP_COMMIT();
    };

    auto COMPUTE = [&](int t) {
        const float* Sa = smg + (t % 3) * GSTAGE;
        const float* Sb = Sa + GSTW;
#pragma unroll
        for (int ks = 0; ks < 2; ++ks) {
            uint32_t af[2][4], bf[8][2];
#pragma unroll
            for (int mt = 0; mt < 2; ++mt) {
                const float* p = Sa + (wm * 32 + mt * 16 + lg) * GP
                               + ks * 8 + lq;
                af[mt][0] = tf32u_(p[0]);
                af[mt][2] = tf32u_(p[4]);
                af[mt][1] = tf32u_(p[8 * GP]);
                af[mt][3] = tf32u_(p[8 * GP + 4]);
            }
#pragma unroll
            for (int nt = 0; nt < 8; ++nt) {
                const float* p = Sb + (wn * 64 + nt * 8 + lg) * GP
                               + ks * 8 + lq;
                bf[nt][0] = tf32u_(p[0]);
                bf[nt][1] = tf32u_(p[4]);
            }
#pragma unroll
            for (int mt = 0; mt < 2; ++mt)
#pragma unroll
                for (int nt = 0; nt < 8; ++nt)
                    mma_tf32_(acc[mt][nt], af[mt], bf[nt]);
        }
    };

    const int ntile = K >> 4;
    ISSUE(0);
    if (ntile > 1) ISSUE(1);
    for (int t = 0; t < ntile; ++t) {
        if (t + 2 < ntile) { ISSUE(t + 2); CP_WAIT2(); }
        else if (t + 1 < ntile) { CP_WAIT1(); }
        else { CP_WAIT0(); }
        __syncthreads();
        COMPUTE(t);
        __syncthreads();
    }

#pragma unroll
    for (int mt = 0; mt < 2; ++mt) {
        int r0 = m0 + wm * 32 + mt * 16 + lg;
#pragma unroll
        for (int nt = 0; nt < 8; ++nt) {
            int c = n0 + wn * 64 + nt * 8 + 2 * lq;
            *(float2*)(C + (size_t)r0 * N + c) =
                make_float2(acc[mt][nt][0], acc[mt][nt][1]);
            *(float2*)(C + (size_t)(r0 + 8) * N + c) =
                make_float2(acc[mt][nt][2], acc[mt][nt][3]);
        }
    }
}

// ====== RMSNorm + RoPE + transpose, warp-per-head, tf32-rounded output =====
__global__ __launch_bounds__(256)
void qkv_post(const float* __restrict__ qkv,
              const float* __restrict__ qw, const float* __restrict__ kw,
              float* __restrict__ q_out, float* __restrict__ k_out,
              float* __restrict__ v_out) {
    const int gwarp = blockIdx.x * 8 + (threadIdx.x >> 5);
    const int lane  = threadIdx.x & 31;
    const int h  = gwarp % 24;
    const int bs = gwarp / 24;
    const int s  = bs & (SEQ - 1);
    const int b  = bs >> 11;

    float4 x = *(const float4*)(qkv + (size_t)bs * QKV_OUT + h * HD + 4 * lane);

    if (h < 20) {
        float ss = x.x * x.x + x.y * x.y + x.z * x.z + x.w * x.w;
#pragma unroll
        for (int o = 16; o; o >>= 1) ss += __shfl_xor_sync(~0u, ss, o);
        float rinv = rsqrtf(ss * (1.0f / HD) + 1e-5f);
        const float* wp = (h < 16) ? qw : kw;
        float4 w = *(const float4*)(wp + 4 * lane);
        x.x *= rinv * w.x; x.y *= rinv * w.y;
        x.z *= rinv * w.z; x.w *= rinv * w.w;
        float4 p;
        p.x = __shfl_xor_sync(~0u, x.x, 16);
        p.y = __shfl_xor_sync(~0u, x.y, 16);
        p.z = __shfl_xor_sync(~0u, x.z, 16);
        p.w = __shfl_xor_sync(~0u, x.w, 16);
        const int i0 = 4 * (lane & 15);
        const bool lo = lane < 16;
        float out[4], xv[4] = {x.x, x.y, x.z, x.w}, pv[4] = {p.x, p.y, p.z, p.w};
#pragma unroll
        for (int j = 0; j < 4; ++j) {
            float inv_freq = exp2f(-(float)(2 * (i0 + j)) * (1.0f / 128.0f)
                                   * 13.28771237954945f);
            float sn, cs;
            sincosf((float)s * inv_freq, &sn, &cs);
            float x1 = lo ? xv[j] : pv[j];
            float x2 = lo ? pv[j] : xv[j];
            out[j] = lo ? (x1 * cs - x2 * sn) : (x1 * sn + x2 * cs);
        }
        float4 o4 = tf32r4_(make_float4(out[0], out[1], out[2], out[3]));
        if (h < 16)
            *(float4*)(q_out + (((size_t)b * NH + h) * SEQ + s) * HD + 4 * lane) = o4;
        else
            *(float4*)(k_out + (((size_t)b * NKV + (h - 16)) * SEQ + s) * HD + 4 * lane) = o4;
    } else {
        *(float4*)(v_out + (((size_t)b * NKV + (h - 20)) * SEQ + s) * HD + 4 * lane) =
            tf32r4_(x);
    }
}

// ========== gate = sigmoid(x . w_gate[h] + b), w_gate staged in smem =======
#define GATE_SMEM (NH * DMODEL * 4)   // 131072

__global__ __launch_bounds__(256)
void gate_kernel(const float* __restrict__ x, const float* __restrict__ wg,
                 const float* __restrict__ bg, float* __restrict__ gate) {
    extern __shared__ float ws[];
    const int tid = threadIdx.x;
    const int lane = tid & 31;
    const int warp = tid >> 5;
    for (int i = tid; i < NH * DMODEL / 4; i += 256)
        ((float4*)ws)[i] = ((const float4*)wg)[i];
    __syncthreads();

    const int r0 = blockIdx.x * 32;
#pragma unroll 1
    for (int rr = 0; rr < 4; ++rr) {
        const int row = r0 + warp + 8 * rr;
        const float4* xv = (const float4*)(x + (size_t)row * DMODEL);
        float acc[NH];
#pragma unroll
        for (int h = 0; h < NH; ++h) acc[h] = 0.f;
#pragma unroll 4
        for (int it = 0; it < 16; ++it) {
            int i4 = lane + 32 * it;
            float4 a = xv[i4];
#pragma unroll
            for (int h = 0; h < NH; ++h) {
                float4 w = ((const float4*)ws)[h * (DMODEL / 4) + i4];
                acc[h] += a.x * w.x + a.y * w.y + a.z * w.z + a.w * w.w;
            }
        }
#pragma unroll
        for (int h = 0; h < NH; ++h) {
            float v = acc[h];
#pragma unroll
            for (int o = 16; o; o >>= 1) v += __shfl_xor_sync(~0u, v, o);
            if (lane == 0)
                gate[(size_t)row * NH + h] =
                    1.0f / (1.0f + __expf(-(v + bg[h])));
        }
    }
}

// ====== causal flash attention (tf32 mma, double-buffered cp.async KV) =====
// CTA: 64 q x 32 kv per iter, 4 warps; 2-stage KV pipeline; 2 CTAs/SM.
#define FBM 64
#define FBN 32
#define FQP 132
#define FKP 132
#define FVP 136
#define KVW (FBN*FKP + FBN*FVP)                       // 8576 words per stage
#define FLASH_SMEM ((FBM*FQP + 2*KVW) * 4)            // 102400 B

__global__ __launch_bounds__(128, 2)
void flash_mma(const float* __restrict__ Q, const float* __restrict__ Kt,
               const float* __restrict__ V, const float* __restrict__ gate,
               float* __restrict__ Oout) {
    extern __shared__ float sm[];
    float* Qs = sm;                               // [64][132]
    float* Kst[2] = { Qs + FBM * FQP,  Qs + FBM * FQP + KVW };
    float* Vst[2] = { Kst[0] + FBN * FKP, Kst[1] + FBN * FKP };
    const uint32_t sQ  = smem_u32_(Qs);
    const uint32_t sK0 = smem_u32_(Kst[0]);
    const uint32_t sV0 = smem_u32_(Vst[0]);

    // longest-work CTAs first: reverse q-tile mapping
    const int qt = gridDim.x - 1 - blockIdx.x;
    const int h  = blockIdx.y;
    const int b  = blockIdx.z;
    const int kvh = h >> 2;
    const int tid = threadIdx.x;
    const int lane = tid & 31;
    const int w = tid >> 5;
    const int lg = lane >> 2;
    const int lq = lane & 3;
    const int q0 = qt * FBM;

    const float* Qg = Q  + (((size_t)b * NH + h) * SEQ + q0) * HD;
    const float* Kg = Kt + ((size_t)b * NKV + kvh) * SEQ * HD;
    const float* Vg = V  + ((size_t)b * NKV + kvh) * SEQ * HD;

    // 32 rows x 128 floats = 1024 f4-chunks per operand; 128 thr -> 8 each
    auto ISSUE_KV = [&](int t) {
        const int s  = t & 1;
        const int k0 = t * FBN;
        const uint32_t bK = sK0 + (uint32_t)(s * KVW) * 4;
        const uint32_t bV = sV0 + (uint32_t)(s * KVW) * 4;
#pragma unroll
        for (int i = 0; i < 8; ++i) {
            int idx = tid + 128 * i;
            int row = idx >> 5, c4 = idx & 31;
            cpa16_(bK + (uint32_t)(row * FKP + 4 * c4) * 4,
                   Kg + (size_t)(k0 + row) * HD + 4 * c4);
        }
#pragma unroll
        for (int i = 0; i < 8; ++i) {
            int idx = tid + 128 * i;
            int row = idx >> 5, c4 = idx & 31;
            cpa16_(bV + (uint32_t)(row * FVP + 4 * c4) * 4,
                   Vg + (size_t)(k0 + row) * HD + 4 * c4);
        }
        CP_COMMIT();
    };

    const int nkt = 2 * qt + 2;

    // prologue: Q (group), KV(0), KV(1); wait for Q+KV0, keep KV1 in flight
    {
#pragma unroll
        for (int i = 0; i < 16; ++i) {
            int idx = tid + 128 * i;
            int row = idx >> 5, c4 = idx & 31;
            cpa16_(sQ + (uint32_t)(row * FQP + 4 * c4) * 4,
                   Qg + (size_t)row * HD + 4 * c4);
        }
        CP_COMMIT();
        ISSUE_KV(0);
        ISSUE_KV(1);          // nkt >= 2 always
        CP_WAIT1();
        __syncthreads();
    }

    float mi[2] = { -1e30f, -1e30f }, li[2] = { 0.f, 0.f };
    float o[16][4];
#pragma unroll
    for (int nt = 0; nt < 16; ++nt)
#pragma unroll
        for (int j = 0; j < 4; ++j) o[nt][j] = 0.f;

    const float scl = 0.08838834764831845f;   // 1/sqrt(128)

    for (int t = 0; t < nkt; ++t) {
        const int s  = t & 1;
        const int k0 = t * FBN;
        const float* Ks = Kst[s];
        const float* Vs = Vst[s];

        // ---- S = Q K^T ----
        float sc[4][4];
#pragma unroll
        for (int nt = 0; nt < 4; ++nt)
#pragma unroll
            for (int j = 0; j < 4; ++j) sc[nt][j] = 0.f;

#pragma unroll
        for (int ks = 0; ks < 16; ++ks) {
            const float* pa = Qs + (16 * w + lg) * FQP + 8 * ks + lq;
            uint32_t a[4];
            a[0] = __float_as_uint(pa[0]);
            a[1] = __float_as_uint(pa[8 * FQP]);
            a[2] = __float_as_uint(pa[4]);
            a[3] = __float_as_uint(pa[8 * FQP + 4]);
#pragma unroll
            for (int nt = 0; nt < 4; ++nt) {
                const float* pb = Ks + (8 * nt + lg) * FKP + 8 * ks + lq;
                uint32_t bf[2];
                bf[0] = __float_as_uint(pb[0]);
                bf[1] = __float_as_uint(pb[4]);
                mma_tf32_(sc[nt], a, bf);
            }
        }

        // ---- scale + causal mask (last two k-tiles only) ----
        const int qr0 = q0 + 16 * w + lg;
        const int qr1 = qr0 + 8;
        const bool needmask = (t >= nkt - 2);
#pragma unroll
        for (int nt = 0; nt < 4; ++nt) {
            int c0 = k0 + 8 * nt + 2 * lq, c1 = c0 + 1;
            float s0 = sc[nt][0] * scl, s1 = sc[nt][1] * scl;
            float s2 = sc[nt][2] * scl, s3 = sc[nt][3] * scl;
            if (needmask) {
                if (c0 > qr0) s0 = -1e30f;
                if (c1 > qr0) s1 = -1e30f;
                if (c0 > qr1) s2 = -1e30f;
                if (c1 > qr1) s3 = -1e30f;
            }
            sc[nt][0] = s0; sc[nt][1] = s1; sc[nt][2] = s2; sc[nt][3] = s3;
        }

        // ---- online softmax ----
#pragma unroll
        for (int r = 0; r < 2; ++r) {
            float m = -1e30f;
#pragma unroll
            for (int nt = 0; nt < 4; ++nt)
                m = fmaxf(m, fmaxf(sc[nt][2 * r], sc[nt][2 * r + 1]));
            m = fmaxf(m, __shfl_xor_sync(~0u, m, 1));
            m = fmaxf(m, __shfl_xor_sync(~0u, m, 2));
            float newm = fmaxf(mi[r], m);
            float esc = __expf(mi[r] - newm);
            mi[r] = newm;
            float rs = 0.f;
#pragma unroll
            for (int nt = 0; nt < 4; ++nt) {
                float p0 = __expf(sc[nt][2 * r]     - newm);
                float p1 = __expf(sc[nt][2 * r + 1] - newm);
                sc[nt][2 * r] = p0; sc[nt][2 * r + 1] = p1;
                rs += p0 + p1;
            }
            rs += __shfl_xor_sync(~0u, rs, 1);
            rs += __shfl_xor_sync(~0u, rs, 2);
            li[r] = li[r] * esc + rs;
#pragma unroll
            for (int nt = 0; nt < 16; ++nt) {
                o[nt][2 * r]     *= esc;
                o[nt][2 * r + 1] *= esc;
            }
        }

        // ---- O += P V  (P frags via shuffles; V raw [kv][136]) ----
        const int src0 = (lane & ~3) | (lq >> 1);
        const int src1 = src0 + 2;
        const bool odd = lq & 1;
#pragma unroll
        for (int j = 0; j < 4; ++j) {
            float p00 = __shfl_sync(~0u, sc[j][0], src0);
            float p01 = __shfl_sync(~0u, sc[j][1], src0);
            float p02 = __shfl_sync(~0u, sc[j][2], src0);
            float p03 = __shfl_sync(~0u, sc[j][3], src0);
            float q00 = __shfl_sync(~0u, sc[j][0], src1);
            float q01 = __shfl_sync(~0u, sc[j][1], src1);
            float q02 = __shfl_sync(~0u, sc[j][2], src1);
            float q03 = __shfl_sync(~0u, sc[j][3], src1);
            uint32_t a[4];
            a[0] = tf32u_(odd ? p01 : p00);
            a[1] = tf32u_(odd ? p03 : p02);
            a[2] = tf32u_(odd ? q01 : q00);
            a[3] = tf32u_(odd ? q03 : q02);
            const float* pv0 = Vs + (8 * j + lq) * FVP + lg;
#pragma unroll
            for (int nt = 0; nt < 16; ++nt) {
                uint32_t bf[2];
                bf[0] = __float_as_uint(pv0[8 * nt]);
                bf[1] = __float_as_uint(pv0[4 * FVP + 8 * nt]);
                mma_tf32_(o[nt], a, bf);
            }
        }

        // ---- pipeline: refill stage s with KV(t+2) while t+1 computes ----
        __syncthreads();                       // all warps done with stage s
        if (t + 2 < nkt) {
            ISSUE_KV(t + 2);
            CP_WAIT1();                        // KV(t+1) arrived; t+2 in flight
            __syncthreads();
        } else if (t + 1 < nkt) {
            CP_WAIT0();                        // KV(t+1) arrived
            __syncthreads();
        }
    }

    // ---- epilogue: /li, *gate, scatter to [B,S,H*hd] ----
#pragma unroll
    for (int r = 0; r < 2; ++r) {
        int row = q0 + 16 * w + lg + 8 * r;
        float g = gate[((size_t)b * SEQ + row) * NH + h];
        float inv = g / li[r];
        float* dst = Oout + ((size_t)(b * SEQ + row)) * (NH * HD) + h * HD;
#pragma unroll
        for (int nt = 0; nt < 16; ++nt) {
            *(float2*)(dst + 8 * nt + 2 * lq) =
                make_float2(o[nt][2 * r] * inv, o[nt][2 * r + 1] * inv);
        }
    }
}

// ================================ launch ===================================
extern "C" void kernel_launch(void* const* d_in, const int* in_sizes, int n_in,
                              void* d_out, int out_size) {
    const float* x      = (const float*)d_in[0];
    const float* w_qkv  = (const float*)d_in[1];
    const float* qnw    = (const float*)d_in[2];
    const float* knw    = (const float*)d_in[3];
    const float* w_gate = (const float*)d_in[4];
    const float* b_gate = (const float*)d_in[5];
    const float* w_o    = (const float*)d_in[6];
    float* out = (float*)d_out;

    float *qkv, *q, *k, *v, *gate, *attn;
    cudaGetSymbolAddress((void**)&qkv,  g_qkv);
    cudaGetSymbolAddress((void**)&q,    g_q);
    cudaGetSymbolAddress((void**)&k,    g_k);
    cudaGetSymbolAddress((void**)&v,    g_v);
    cudaGetSymbolAddress((void**)&gate, g_gate);
    cudaGetSymbolAddress((void**)&attn, g_attn);

    cudaFuncSetAttribute(gemm_tf32mma,
                         cudaFuncAttributeMaxDynamicSharedMemorySize, GEMM_SMEM);
    cudaFuncSetAttribute(flash_mma,
                         cudaFuncAttributeMaxDynamicSharedMemorySize, FLASH_SMEM);
    cudaFuncSetAttribute(gate_kernel,
                         cudaFuncAttributeMaxDynamicSharedMemorySize, GATE_SMEM);

    // 1) QKV projection: [4096,2048] x [3072,2048]^T
    {
        dim3 grid(QKV_OUT / 128, BSTOT / 128);
        gemm_tf32mma<<<grid, 256, GEMM_SMEM>>>(x, w_qkv, qkv, BSTOT, QKV_OUT, DMODEL);
    }
    // 2) RMSNorm + RoPE + layout (warp per head; writes tf32-rounded q/k/v)
    {
        qkv_post<<<(BSTOT * 24) / 8, 256>>>(qkv, qnw, knw, q, k, v);
    }
    // 3) gate (w_gate staged in smem)
    {
        gate_kernel<<<BSTOT / 32, 256, GATE_SMEM>>>(x, w_gate, b_gate, gate);
    }
    // 4) flash attention, tf32 mma, 2-stage KV pipeline (gated epilogue)
    {
        dim3 grid(SEQ / FBM, NH, BATCH);
        flash_mma<<<grid, 128, FLASH_SMEM>>>(q, k, v, gate, attn);
    }
    // 5) output projection: [4096,2048] x [2048,2048]^T -> d_out
    {
        dim3 grid(DMODEL / 128, BSTOT / 128);
        gemm_tf32mma<<<grid, 256, GEMM_SMEM>>>(attn, w_o, out, BSTOT, DMODEL, DMODEL);
    }
}

// round 12
// speedup vs baseline: 1.0895x; 1.0895x over previous
#include <cuda_runtime.h>
#include <cuda_bf16.h>
#include <math.h>
#include <cstdint>

#define BATCH 2
#define SEQ 2048
#define DMODEL 2048
#define NH 16
#define NKV 4
#define HD 128
#define NREP 4
#define QKV_OUT 3072   // (16 + 2*4) * 128
#define BSTOT (BATCH*SEQ)

// ---------------- scratch (device globals; no allocation allowed) ----------
__device__ float g_qkv [BSTOT * QKV_OUT];        // 48 MB
__device__ float g_q   [BATCH * NH  * SEQ * HD]; // 32 MB  (tf32-rounded)
__device__ float g_k   [BATCH * NKV * SEQ * HD]; //  8 MB  (tf32-rounded)
__device__ float g_v   [BATCH * NKV * SEQ * HD]; //  8 MB  (tf32-rounded)
__device__ float g_gate[BSTOT * NH];             // 0.5 MB
__device__ float g_attn[BSTOT * (NH*HD)];        // 32 MB
__device__ float2 g_rope[SEQ * 64];              // 1 MB (cos,sin per (s,i))

// ========================== helpers ========================================
__device__ __forceinline__ float tf32r_(float x) {
    uint32_t r;
    asm("cvt.rna.tf32.f32 %0, %1;" : "=r"(r) : "f"(x));
    return __uint_as_float(r);
}
__device__ __forceinline__ uint32_t tf32u_(float x) {
    uint32_t r;
    asm("cvt.rna.tf32.f32 %0, %1;" : "=r"(r) : "f"(x));
    return r;
}
__device__ __forceinline__ float4 tf32r4_(float4 v) {
    v.x = tf32r_(v.x); v.y = tf32r_(v.y);
    v.z = tf32r_(v.z); v.w = tf32r_(v.w);
    return v;
}
__device__ __forceinline__ uint32_t smem_u32_(const void* p) {
    uint32_t a;
    asm("{ .reg .u64 t; cvta.to.shared.u64 t, %1; cvt.u32.u64 %0, t; }"
        : "=r"(a) : "l"(p));
    return a;
}
__device__ __forceinline__ void cpa16_(uint32_t dst, const void* src) {
    asm volatile("cp.async.cg.shared.global [%0], [%1], 16;"
                 :: "r"(dst), "l"(src));
}
#define CP_COMMIT() asm volatile("cp.async.commit_group;" ::: "memory")
#define CP_WAIT0()  asm volatile("cp.async.wait_group 0;" ::: "memory")
#define CP_WAIT1()  asm volatile("cp.async.wait_group 1;" ::: "memory")
#define CP_WAIT2()  asm volatile("cp.async.wait_group 2;" ::: "memory")

// D += A(16x8,row) * B(8x8,col)  tf32 inputs, f32 accum
__device__ __forceinline__ void mma_tf32_(float* d, const uint32_t* a,
                                          const uint32_t* b) {
    asm volatile(
        "mma.sync.aligned.m16n8k8.row.col.f32.tf32.tf32.f32 "
        "{%0,%1,%2,%3}, {%4,%5,%6,%7}, {%8,%9}, {%0,%1,%2,%3};\n"
        : "+f"(d[0]), "+f"(d[1]), "+f"(d[2]), "+f"(d[3])
        : "r"(a[0]), "r"(a[1]), "r"(a[2]), "r"(a[3]),
          "r"(b[0]), "r"(b[1]));
}

// ======================= rope table: cos/sin per (s,i) =====================
__global__ __launch_bounds__(256)
void rope_table(float2* __restrict__ tab) {
    int idx = blockIdx.x * 256 + threadIdx.x;   // 0 .. SEQ*64-1
    int s = idx >> 6, i = idx & 63;
    float inv_freq = exp2f(-(float)(2 * i) * (1.0f / 128.0f)
                           * 13.28771237954945f);  // log2(10000)
    float sn, cs;
    sincosf((float)s * inv_freq, &sn, &cs);
    tab[idx] = make_float2(cs, sn);
}

// ===== tf32 mma.sync NT GEMM, cp.async 3-stage: C[M,N] = A * B^T ===========
// 128x128 CTA tile, BK=16, 8 warps (warp tile 32x64), pitch-20 smem.
#define GP 20
#define GSTW (128 * GP)          // words per operand per stage
#define GSTAGE (2 * GSTW)        // A+B per stage
#define GEMM_SMEM (3 * GSTAGE * 4)  // 61440 bytes

__global__ __launch_bounds__(256, 2)
void gemm_tf32mma(const float* __restrict__ A, const float* __restrict__ Bm,
                  float* __restrict__ C, int M, int N, int K) {
    extern __shared__ float smg[];
    const uint32_t sb = smem_u32_(smg);

    const int tid  = threadIdx.x;
    const int lane = tid & 31;
    const int wid  = tid >> 5;
    const int wm   = wid & 3;
    const int wn   = wid >> 2;
    const int m0   = blockIdx.y * 128;
    const int n0   = blockIdx.x * 128;
    const int lg   = lane >> 2;
    const int lq   = lane & 3;

    float acc[2][8][4];
#pragma unroll
    for (int mt = 0; mt < 2; ++mt)
#pragma unroll
        for (int nt = 0; nt < 8; ++nt)
#pragma unroll
            for (int j = 0; j < 4; ++j) acc[mt][nt][j] = 0.f;

    const int row_ld = tid >> 2;         // 0..63 (handles 2 rows via +64)
    const int c4_ld  = tid & 3;

    auto ISSUE = [&](int t) {
        const int st = (t % 3);
        const int k0 = t << 4;
        const uint32_t base = sb + (uint32_t)(st * GSTAGE) * 4;
#pragma unroll
        for (int i = 0; i < 2; ++i) {
            int row = row_ld + 64 * i;
            uint32_t off = (uint32_t)(row * GP + 4 * c4_ld) * 4;
            cpa16_(base + off,
                   A + (size_t)(m0 + row) * K + k0 + 4 * c4_ld);
            cpa16_(base + (uint32_t)GSTW * 4 + off,
                   Bm + (size_t)(n0 + row) * K + k0 + 4 * c4_ld);
        }
        CP_COMMIT();
    };

    auto COMPUTE = [&](int t) {
        const float* Sa = smg + (t % 3) * GSTAGE;
        const float* Sb = Sa + GSTW;
#pragma unroll
        for (int ks = 0; ks < 2; ++ks) {
            uint32_t af[2][4], bf[8][2];
#pragma unroll
            for (int mt = 0; mt < 2; ++mt) {
                const float* p = Sa + (wm * 32 + mt * 16 + lg) * GP
                               + ks * 8 + lq;
                af[mt][0] = tf32u_(p[0]);
                af[mt][2] = tf32u_(p[4]);
                af[mt][1] = tf32u_(p[8 * GP]);
                af[mt][3] = tf32u_(p[8 * GP + 4]);
            }
#pragma unroll
            for (int nt = 0; nt < 8; ++nt) {
                const float* p = Sb + (wn * 64 + nt * 8 + lg) * GP
                               + ks * 8 + lq;
                bf[nt][0] = tf32u_(p[0]);
                bf[nt][1] = tf32u_(p[4]);
            }
#pragma unroll
            for (int mt = 0; mt < 2; ++mt)
#pragma unroll
                for (int nt = 0; nt < 8; ++nt)
                    mma_tf32_(acc[mt][nt], af[mt], bf[nt]);
        }
    };

    const int ntile = K >> 4;
    ISSUE(0);
    if (ntile > 1) ISSUE(1);
    for (int t = 0; t < ntile; ++t) {
        if (t + 2 < ntile) { ISSUE(t + 2); CP_WAIT2(); }
        else if (t + 1 < ntile) { CP_WAIT1(); }
        else { CP_WAIT0(); }
        __syncthreads();
        COMPUTE(t);
        __syncthreads();
    }

#pragma unroll
    for (int mt = 0; mt < 2; ++mt) {
        int r0 = m0 + wm * 32 + mt * 16 + lg;
#pragma unroll
        for (int nt = 0; nt < 8; ++nt) {
            int c = n0 + wn * 64 + nt * 8 + 2 * lq;
            *(float2*)(C + (size_t)r0 * N + c) =
                make_float2(acc[mt][nt][0], acc[mt][nt][1]);
            *(float2*)(C + (size_t)(r0 + 8) * N + c) =
                make_float2(acc[mt][nt][2], acc[mt][nt][3]);
        }
    }
}

// ====== RMSNorm + RoPE (table) + transpose, warp-per-head, tf32 output =====
__global__ __launch_bounds__(256)
void qkv_post(const float* __restrict__ qkv,
              const float* __restrict__ qw, const float* __restrict__ kw,
              const float2* __restrict__ rope,
              float* __restrict__ q_out, float* __restrict__ k_out,
              float* __restrict__ v_out) {
    const int gwarp = blockIdx.x * 8 + (threadIdx.x >> 5);
    const int lane  = threadIdx.x & 31;
    const int h  = gwarp % 24;
    const int bs = gwarp / 24;
    const int s  = bs & (SEQ - 1);
    const int b  = bs >> 11;

    float4 x = *(const float4*)(qkv + (size_t)bs * QKV_OUT + h * HD + 4 * lane);

    if (h < 20) {
        float ss = x.x * x.x + x.y * x.y + x.z * x.z + x.w * x.w;
#pragma unroll
        for (int o = 16; o; o >>= 1) ss += __shfl_xor_sync(~0u, ss, o);
        float rinv = rsqrtf(ss * (1.0f / HD) + 1e-5f);
        const float* wp = (h < 16) ? qw : kw;
        float4 w = *(const float4*)(wp + 4 * lane);
        x.x *= rinv * w.x; x.y *= rinv * w.y;
        x.z *= rinv * w.z; x.w *= rinv * w.w;
        float4 p;
        p.x = __shfl_xor_sync(~0u, x.x, 16);
        p.y = __shfl_xor_sync(~0u, x.y, 16);
        p.z = __shfl_xor_sync(~0u, x.z, 16);
        p.w = __shfl_xor_sync(~0u, x.w, 16);
        const int i0 = 4 * (lane & 15);
        const bool lo = lane < 16;
        float out[4], xv[4] = {x.x, x.y, x.z, x.w}, pv[4] = {p.x, p.y, p.z, p.w};
        const float2* rp = rope + s * 64 + i0;
#pragma unroll
        for (int j = 0; j < 4; ++j) {
            float2 cssn = rp[j];
            float x1 = lo ? xv[j] : pv[j];
            float x2 = lo ? pv[j] : xv[j];
            out[j] = lo ? (x1 * cssn.x - x2 * cssn.y)
                        : (x1 * cssn.y + x2 * cssn.x);
        }
        float4 o4 = tf32r4_(make_float4(out[0], out[1], out[2], out[3]));
        if (h < 16)
            *(float4*)(q_out + (((size_t)b * NH + h) * SEQ + s) * HD + 4 * lane) = o4;
        else
            *(float4*)(k_out + (((size_t)b * NKV + (h - 16)) * SEQ + s) * HD + 4 * lane) = o4;
    } else {
        *(float4*)(v_out + (((size_t)b * NKV + (h - 20)) * SEQ + s) * HD + 4 * lane) =
            tf32r4_(x);
    }
}

// ========== gate = sigmoid(x . w_gate[h] + b), w_gate staged in smem =======
#define GATE_SMEM (NH * DMODEL * 4)   // 131072

__global__ __launch_bounds__(256)
void gate_kernel(const float* __restrict__ x, const float* __restrict__ wg,
                 const float* __restrict__ bg, float* __restrict__ gate) {
    extern __shared__ float ws[];
    const int tid = threadIdx.x;
    const int lane = tid & 31;
    const int warp = tid >> 5;
    for (int i = tid; i < NH * DMODEL / 4; i += 256)
        ((float4*)ws)[i] = ((const float4*)wg)[i];
    __syncthreads();

    const int r0 = blockIdx.x * 32;
#pragma unroll 1
    for (int rr = 0; rr < 4; ++rr) {
        const int row = r0 + warp + 8 * rr;
        const float4* xv = (const float4*)(x + (size_t)row * DMODEL);
        float acc[NH];
#pragma unroll
        for (int h = 0; h < NH; ++h) acc[h] = 0.f;
#pragma unroll 4
        for (int it = 0; it < 16; ++it) {
            int i4 = lane + 32 * it;
            float4 a = xv[i4];
#pragma unroll
            for (int h = 0; h < NH; ++h) {
                float4 w = ((const float4*)ws)[h * (DMODEL / 4) + i4];
                acc[h] += a.x * w.x + a.y * w.y + a.z * w.z + a.w * w.w;
            }
        }
#pragma unroll
        for (int h = 0; h < NH; ++h) {
            float v = acc[h];
#pragma unroll
            for (int o = 16; o; o >>= 1) v += __shfl_xor_sync(~0u, v, o);
            if (lane == 0)
                gate[(size_t)row * NH + h] =
                    1.0f / (1.0f + __expf(-(v + bg[h])));
        }
    }
}

// =========== causal flash attention (tf32 mma.sync, cp.async K/V) ==========
// CTA: 64 q x 64 kv, 4 warps (16 q-rows each); 2 CTAs/SM (100 KB smem).
// (R10 configuration — proven fastest.)
#define FBM 64
#define FBN 64
#define FQP 132
#define FKP 132
#define FVP 136
#define FLASH_SMEM ((FBM*FQP + FBN*FKP + FBN*FVP) * 4)   // 102400 B

__global__ __launch_bounds__(128, 2)
void flash_mma(const float* __restrict__ Q, const float* __restrict__ Kt,
               const float* __restrict__ V, const float* __restrict__ gate,
               float* __restrict__ Oout) {
    extern __shared__ float sm[];
    float* Qs = sm;                       // [64][132]
    float* Ks = Qs + FBM * FQP;           // [64][132]  (kv, hd)
    float* Vs = Ks + FBN * FKP;           // [64][136]  (kv, hd) raw
    const uint32_t sQ = smem_u32_(Qs);
    const uint32_t sK = smem_u32_(Ks);
    const uint32_t sV = smem_u32_(Vs);

    const int qt = blockIdx.x;
    const int h  = blockIdx.y;
    const int b  = blockIdx.z;
    const int kvh = h >> 2;
    const int tid = threadIdx.x;
    const int lane = tid & 31;
    const int w = tid >> 5;
    const int lg = lane >> 2;
    const int lq = lane & 3;
    const int q0 = qt * FBM;

    const float* Qg = Q  + (((size_t)b * NH + h) * SEQ + q0) * HD;
    const float* Kg = Kt + ((size_t)b * NKV + kvh) * SEQ * HD;
    const float* Vg = V  + ((size_t)b * NKV + kvh) * SEQ * HD;

    auto ISSUE_KV = [&](int t) {
        const int k0 = t * FBN;
#pragma unroll
        for (int i = 0; i < 16; ++i) {
            int idx = tid + 128 * i;
            int row = idx >> 5, c4 = idx & 31;
            cpa16_(sK + (uint32_t)(row * FKP + 4 * c4) * 4,
                   Kg + (size_t)(k0 + row) * HD + 4 * c4);
        }
#pragma unroll
        for (int i = 0; i < 16; ++i) {
            int idx = tid + 128 * i;
            int row = idx >> 5, c4 = idx & 31;
            cpa16_(sV + (uint32_t)(row * FVP + 4 * c4) * 4,
                   Vg + (size_t)(k0 + row) * HD + 4 * c4);
        }
        CP_COMMIT();
    };

    // prologue: Q + first K/V tile
    {
#pragma unroll
        for (int i = 0; i < 16; ++i) {
            int idx = tid + 128 * i;
            int row = idx >> 5, c4 = idx & 31;
            cpa16_(sQ + (uint32_t)(row * FQP + 4 * c4) * 4,
                   Qg + (size_t)row * HD + 4 * c4);
        }
        CP_COMMIT();
        ISSUE_KV(0);
        CP_WAIT0();
        __syncthreads();
    }

    float mi[2] = { -1e30f, -1e30f }, li[2] = { 0.f, 0.f };
    float o[16][4];
#pragma unroll
    for (int nt = 0; nt < 16; ++nt)
#pragma unroll
        for (int j = 0; j < 4; ++j) o[nt][j] = 0.f;

    const float scl = 0.08838834764831845f;   // 1/sqrt(128)
    const int nkt = qt + 1;

    for (int t = 0; t < nkt; ++t) {
        const int k0 = t * FBN;

        // ---- S = Q K^T ----
        float sc[8][4];
#pragma unroll
        for (int nt = 0; nt < 8; ++nt)
#pragma unroll
            for (int j = 0; j < 4; ++j) sc[nt][j] = 0.f;

#pragma unroll
        for (int ks = 0; ks < 16; ++ks) {
            const float* pa = Qs + (16 * w + lg) * FQP + 8 * ks + lq;
            uint32_t a[4];
            a[0] = __float_as_uint(pa[0]);
            a[1] = __float_as_uint(pa[8 * FQP]);
            a[2] = __float_as_uint(pa[4]);
            a[3] = __float_as_uint(pa[8 * FQP + 4]);
#pragma unroll
            for (int nt = 0; nt < 8; ++nt) {
                const float* pb = Ks + (8 * nt + lg) * FKP + 8 * ks + lq;
                uint32_t bf[2];
                bf[0] = __float_as_uint(pb[0]);
                bf[1] = __float_as_uint(pb[4]);
                mma_tf32_(sc[nt], a, bf);
            }
        }

        // ---- scale + causal mask (only diagonal tile t == qt) ----
        const int qr0 = q0 + 16 * w + lg;
        const int qr1 = qr0 + 8;
        const bool needmask = (t == qt);
#pragma unroll
        for (int nt = 0; nt < 8; ++nt) {
            int c0 = k0 + 8 * nt + 2 * lq, c1 = c0 + 1;
            float s0 = sc[nt][0] * scl, s1 = sc[nt][1] * scl;
            float s2 = sc[nt][2] * scl, s3 = sc[nt][3] * scl;
            if (needmask) {
                if (c0 > qr0) s0 = -1e30f;
                if (c1 > qr0) s1 = -1e30f;
                if (c0 > qr1) s2 = -1e30f;
                if (c1 > qr1) s3 = -1e30f;
            }
            sc[nt][0] = s0; sc[nt][1] = s1; sc[nt][2] = s2; sc[nt][3] = s3;
        }

        // ---- online softmax ----
#pragma unroll
        for (int r = 0; r < 2; ++r) {
            float m = -1e30f;
#pragma unroll
            for (int nt = 0; nt < 8; ++nt)
                m = fmaxf(m, fmaxf(sc[nt][2 * r], sc[nt][2 * r + 1]));
            m = fmaxf(m, __shfl_xor_sync(~0u, m, 1));
            m = fmaxf(m, __shfl_xor_sync(~0u, m, 2));
            float newm = fmaxf(mi[r], m);
            float esc = __expf(mi[r] - newm);
            mi[r] = newm;
            float rs = 0.f;
#pragma unroll
            for (int nt = 0; nt < 8; ++nt) {
                float p0 = __expf(sc[nt][2 * r]     - newm);
                float p1 = __expf(sc[nt][2 * r + 1] - newm);
                sc[nt][2 * r] = p0; sc[nt][2 * r + 1] = p1;
                rs += p0 + p1;
            }
            rs += __shfl_xor_sync(~0u, rs, 1);
            rs += __shfl_xor_sync(~0u, rs, 2);
            li[r] = li[r] * esc + rs;
#pragma unroll
            for (int nt = 0; nt < 16; ++nt) {
                o[nt][2 * r]     *= esc;
                o[nt][2 * r + 1] *= esc;
            }
        }

        // ---- O += P V  (P frags via shuffles; V raw [kv][136]) ----
        const int src0 = (lane & ~3) | (lq >> 1);
        const int src1 = src0 + 2;
        const bool odd = lq & 1;
#pragma unroll
        for (int j = 0; j < 8; ++j) {
            float p00 = __shfl_sync(~0u, sc[j][0], src0);
            float p01 = __shfl_sync(~0u, sc[j][1], src0);
            float p02 = __shfl_sync(~0u, sc[j][2], src0);
            float p03 = __shfl_sync(~0u, sc[j][3], src0);
            float q00 = __shfl_sync(~0u, sc[j][0], src1);
            float q01 = __shfl_sync(~0u, sc[j][1], src1);
            float q02 = __shfl_sync(~0u, sc[j][2], src1);
            float q03 = __shfl_sync(~0u, sc[j][3], src1);
            uint32_t a[4];
            a[0] = tf32u_(odd ? p01 : p00);
            a[1] = tf32u_(odd ? p03 : p02);
            a[2] = tf32u_(odd ? q01 : q00);
            a[3] = tf32u_(odd ? q03 : q02);
            const float* pv0 = Vs + (8 * j + lq) * FVP + lg;
#pragma unroll
            for (int nt = 0; nt < 16; ++nt) {
                uint32_t bf[2];
                bf[0] = __float_as_uint(pv0[8 * nt]);
                bf[1] = __float_as_uint(pv0[4 * FVP + 8 * nt]);
                mma_tf32_(o[nt], a, bf);
            }
        }

        if (t + 1 < nkt) {
            __syncthreads();
            ISSUE_KV(t + 1);
            CP_WAIT0();
            __syncthreads();
        }
    }

    // ---- epilogue: /li, *gate, scatter to [B,S,H*hd] ----
#pragma unroll
    for (int r = 0; r < 2; ++r) {
        int row = q0 + 16 * w + lg + 8 * r;
        float g = gate[((size_t)b * SEQ + row) * NH + h];
        float inv = g / li[r];
        float* dst = Oout + ((size_t)(b * SEQ + row)) * (NH * HD) + h * HD;
#pragma unroll
        for (int nt = 0; nt < 16; ++nt) {
            *(float2*)(dst + 8 * nt + 2 * lq) =
                make_float2(o[nt][2 * r] * inv, o[nt][2 * r + 1] * inv);
        }
    }
}

// ================================ launch ===================================
extern "C" void kernel_launch(void* const* d_in, const int* in_sizes, int n_in,
                              void* d_out, int out_size) {
    const float* x      = (const float*)d_in[0];
    const float* w_qkv  = (const float*)d_in[1];
    const float* qnw    = (const float*)d_in[2];
    const float* knw    = (const float*)d_in[3];
    const float* w_gate = (const float*)d_in[4];
    const float* b_gate = (const float*)d_in[5];
    const float* w_o    = (const float*)d_in[6];
    float* out = (float*)d_out;

    float *qkv, *q, *k, *v, *gate, *attn;
    float2* rope;
    cudaGetSymbolAddress((void**)&qkv,  g_qkv);
    cudaGetSymbolAddress((void**)&q,    g_q);
    cudaGetSymbolAddress((void**)&k,    g_k);
    cudaGetSymbolAddress((void**)&v,    g_v);
    cudaGetSymbolAddress((void**)&gate, g_gate);
    cudaGetSymbolAddress((void**)&attn, g_attn);
    cudaGetSymbolAddress((void**)&rope, g_rope);

    cudaFuncSetAttribute(gemm_tf32mma,
                         cudaFuncAttributeMaxDynamicSharedMemorySize, GEMM_SMEM);
    cudaFuncSetAttribute(flash_mma,
                         cudaFuncAttributeMaxDynamicSharedMemorySize, FLASH_SMEM);
    cudaFuncSetAttribute(gate_kernel,
                         cudaFuncAttributeMaxDynamicSharedMemorySize, GATE_SMEM);

    // 0) rope table (cheap; overlaps nothing but costs ~2us)
    rope_table<<<SEQ * 64 / 256, 256>>>(rope);
    // 1) QKV projection: [4096,2048] x [3072,2048]^T
    {
        dim3 grid(QKV_OUT / 128, BSTOT / 128);
        gemm_tf32mma<<<grid, 256, GEMM_SMEM>>>(x, w_qkv, qkv, BSTOT, QKV_OUT, DMODEL);
    }
    // 2) RMSNorm + RoPE(table) + layout (warp per head; tf32-rounded q/k/v)
    {
        qkv_post<<<(BSTOT * 24) / 8, 256>>>(qkv, qnw, knw, rope, q, k, v);
    }
    // 3) gate (w_gate staged in smem)
    {
        gate_kernel<<<BSTOT / 32, 256, GATE_SMEM>>>(x, w_gate, b_gate, gate);
    }
    // 4) flash attention, tf32 mma (gated epilogue) — R10 config
    {
        dim3 grid(SEQ / FBM, NH, BATCH);
        flash_mma<<<grid, 128, FLASH_SMEM>>>(q, k, v, gate, attn);
    }
    // 5) output projection: [4096,2048] x [2048,2048]^T -> d_out
    {
        dim3 grid(DMODEL / 128, BSTOT / 128);
        gemm_tf32mma<<<grid, 256, GEMM_SMEM>>>(attn, w_o, out, BSTOT, DMODEL, DMODEL);
    }
}